// round 10
// baseline (speedup 1.0000x reference)
#include <cuda_runtime.h>
#include <math.h>
#include <cstdint>

// B=8, A=1024, N=64, G=50, F=128
#define A_DIM 1024
#define F_DIM 128
#define G_DIM 50
#define K1STEPS 7          // GEMM1 K = 56 >= 50
#define LOG2F_CONST 0.6931471805599453f

// ---------------- device scratch ----------------
__device__ float g_xw[8 * A_DIM * F_DIM];                // x @ W_in2f  (4 MB)
__device__ float g_y [8 * A_DIM * F_DIM];                // pre-output  (4 MB)
__device__ __align__(16) float g_Wf1v[64 * F_DIM];       // W_f1 pad K=64, frag-permuted
__device__ __align__(16) float g_Wf2v[F_DIM * F_DIM];    // W_f2 frag-permuted

__device__ __forceinline__ float ssp(float x) {
    return fmaxf(x, 0.0f) + __logf(1.0f + __expf(-fabsf(x))) - LOG2F_CONST;
}
__device__ __forceinline__ float tf32r(float x) {
    uint32_t r;
    asm("cvt.rna.tf32.f32 %0, %1;" : "=r"(r) : "f"(x));
    return __uint_as_float(r);
}

// m16n8k8 row.col tf32 MMA. lane: gid=lane>>2, tig=lane&3
//   A: a0=(gid,tig) a1=(gid+8,tig) a2=(gid,tig+4) a3=(gid+8,tig+4)
//   B: b0=(k=tig,n=gid) b1=(k=tig+4,n=gid)
//   D: d0=(gid,2tig) d1=(gid,2tig+1) d2=(gid+8,2tig) d3=(gid+8,2tig+1)
__device__ __forceinline__ void mma8(float* d, const uint32_t* a, uint32_t b0, uint32_t b1) {
    asm volatile(
        "mma.sync.aligned.m16n8k8.row.col.f32.tf32.tf32.f32 "
        "{%0,%1,%2,%3}, {%4,%5,%6,%7}, {%8,%9}, {%0,%1,%2,%3};"
        : "+f"(d[0]), "+f"(d[1]), "+f"(d[2]), "+f"(d[3])
        : "r"(a[0]), "r"(a[1]), "r"(a[2]), "r"(a[3]), "r"(b0), "r"(b1));
}

// ---------------- SMEM layout (R4/R7-proven linear tiles) ----------------
#define FS1 68            // f_ij row stride (floats), conflict-free A pattern
#define HS  132           // h row stride (floats), conflict-free A pattern
#define OFF_B1   0        // b_f1   [128]f
#define OFF_B2   512      // b_f2   [128]f
#define OFF_NBR  1024     // nbr    [128]i
#define OFF_MSK  1536     // mask   [128]f
#define OFF_FIJ  2048     // f_ij   [128][68]f = 34816 B
#define OFF_H    36864    // h / Wm [128][132]f = 67584 B
#define SMEM_TOTAL 104448

// ---------------------------------------------------------------------------
// prep: tf32-round + permute weights to fragment-vector order:
//   Wv[k][half*64 + gid*8 + ni] = W[k][half*64 + ni*8 + gid]
// -> each thread's 8 B-values per k-row are contiguous (2x LDG.128).
// (Column mapping verified correct in R6: identical rel_err.)
// ---------------------------------------------------------------------------
__global__ void prep_kernel(const float* __restrict__ W_f1, const float* __restrict__ W_f2) {
    int t = threadIdx.x;
    for (int i = t; i < 64 * F_DIM; i += blockDim.x) {
        int k = i >> 7, j = i & 127;
        int half = j >> 6, gid = (j >> 3) & 7, ni = j & 7;
        int src = half * 64 + ni * 8 + gid;
        g_Wf1v[i] = (k < G_DIM) ? tf32r(W_f1[k * F_DIM + src]) : 0.0f;
    }
    for (int i = t; i < F_DIM * F_DIM; i += blockDim.x) {
        int k = i >> 7, j = i & 127;
        int half = j >> 6, gid = (j >> 3) & 7, ni = j & 7;
        int src = half * 64 + ni * 8 + gid;
        g_Wf2v[i] = tf32r(W_f2[k * F_DIM + src]);
    }
}

// ---------------------------------------------------------------------------
// dense: out[r, o] = (ssp?)(in[r,:] @ W[:,o] + bias)   — 8 rows per CTA
// ---------------------------------------------------------------------------
__global__ __launch_bounds__(F_DIM) void dense_kernel(
    const float* __restrict__ in, const float* __restrict__ W,
    const float* __restrict__ bias, float* __restrict__ outp, int apply_ssp)
{
    __shared__ float xs[8 * F_DIM];
    const int r0 = blockIdx.x * 8, o = threadIdx.x;
#pragma unroll
    for (int r = 0; r < 8; ++r)
        xs[r * F_DIM + o] = in[(size_t)(r0 + r) * F_DIM + o];
    __syncthreads();

    float a[8];
    float bb = bias ? __ldg(&bias[o]) : 0.0f;
#pragma unroll
    for (int r = 0; r < 8; ++r) a[r] = bb;
#pragma unroll 4
    for (int c = 0; c < F_DIM; ++c) {
        float w = __ldg(&W[c * F_DIM + o]);
#pragma unroll
        for (int r = 0; r < 8; ++r)
            a[r] = fmaf(xs[r * F_DIM + c], w, a[r]);
    }
#pragma unroll
    for (int r = 0; r < 8; ++r)
        outp[(size_t)(r0 + r) * F_DIM + o] = apply_ssp ? ssp(a[r]) : a[r];
}

// ---------------------------------------------------------------------------
// Main: one CTA per 2 atoms (128 rows), 256 threads, 8 warps (4M x 2N).
// R7 structure + vectorized B-fragment loads (2x LDG.128 per k-row).
// ---------------------------------------------------------------------------
__global__ __launch_bounds__(256, 2) void cfconv_mma(
    const float* __restrict__ f_ij,   // [B,A,N,G]
    const float* __restrict__ mask,   // [B,A,N]
    const int*   __restrict__ nbrs,   // [B,A,N]
    const float* __restrict__ b_f1,
    const float* __restrict__ b_f2)
{
    extern __shared__ char smem[];
    float* b1s    = (float*)(smem + OFF_B1);
    float* b2s    = (float*)(smem + OFF_B2);
    int*   nbr_sh = (int*)  (smem + OFF_NBR);
    float* msk_sh = (float*)(smem + OFF_MSK);
    float* fij_s  = (float*)(smem + OFF_FIJ);
    float* h_s    = (float*)(smem + OFF_H);

    const int tid = threadIdx.x, wid = tid >> 5, lane = tid & 31;
    const int gid = lane >> 2, tig = lane & 3;
    const int c = blockIdx.x;          // atoms 2c, 2c+1
    const int b = c >> 9;              // batch

    if (tid < 128) {
        b1s[tid]    = b_f1[tid];
        b2s[tid]    = b_f2[tid];
        nbr_sh[tid] = nbrs[(size_t)c * 128 + tid];
        msk_sh[tid] = mask[(size_t)c * 128 + tid];
    }
    // stage f_ij tile [128 rows][56 cols used], tf32-rounded, zero-pad 50..55
    {
        const float* fb = f_ij + (size_t)c * 128 * G_DIM;
        for (int i = tid; i < 128 * 64; i += 256) {
            int r = i >> 6, cc = i & 63;
            if (cc < 56)
                fij_s[r * FS1 + cc] = (cc < G_DIM) ? tf32r(__ldg(fb + r * G_DIM + cc)) : 0.0f;
        }
    }
    __syncthreads();

    const int n0 = (wid & 3) * 32;     // warp's 32 rows
    const int f0 = (wid >> 2) * 64;    // warp's 64 cols (= permuted half offset)

    // ================= GEMM1: K=56 (7 k-steps) =================
    float acc[16][4];
#pragma unroll
    for (int t = 0; t < 16; ++t) { acc[t][0]=acc[t][1]=acc[t][2]=acc[t][3]=0.f; }

    {
        const uint32_t* fij_u = (const uint32_t*)fij_s;
        const float4*   wv    = (const float4*)g_Wf1v;
#pragma unroll
        for (int ks = 0; ks < K1STEPS; ++ks) {
            const int k0 = ks * 8;
            uint32_t a[2][4];
#pragma unroll
            for (int mi = 0; mi < 2; ++mi) {
                int r = (n0 + mi * 16 + gid) * FS1 + k0 + tig;
                a[mi][0] = fij_u[r];
                a[mi][1] = fij_u[r + 8 * FS1];
                a[mi][2] = fij_u[r + 4];
                a[mi][3] = fij_u[r + 8 * FS1 + 4];
            }
            // B: rows k0+tig, k0+tig+4; 8 contiguous floats each (2x LDG.128)
            int r0i = ((k0 + tig)     * F_DIM + f0 + gid * 8) >> 2;
            int r1i = ((k0 + tig + 4) * F_DIM + f0 + gid * 8) >> 2;
            float4 q0 = __ldg(wv + r0i), q1 = __ldg(wv + r0i + 1);
            float4 s0 = __ldg(wv + r1i), s1 = __ldg(wv + r1i + 1);
            uint32_t bq[8] = {__float_as_uint(q0.x),__float_as_uint(q0.y),__float_as_uint(q0.z),__float_as_uint(q0.w),
                              __float_as_uint(q1.x),__float_as_uint(q1.y),__float_as_uint(q1.z),__float_as_uint(q1.w)};
            uint32_t bs[8] = {__float_as_uint(s0.x),__float_as_uint(s0.y),__float_as_uint(s0.z),__float_as_uint(s0.w),
                              __float_as_uint(s1.x),__float_as_uint(s1.y),__float_as_uint(s1.z),__float_as_uint(s1.w)};
#pragma unroll
            for (int ni = 0; ni < 8; ++ni) {
                mma8(acc[0 * 8 + ni], a[0], bq[ni], bs[ni]);
                mma8(acc[1 * 8 + ni], a[1], bq[ni], bs[ni]);
            }
        }
    }

    // ---- epi1: h = tf32(ssp(D1 + b1)) -> linear SMEM ----
#pragma unroll
    for (int mi = 0; mi < 2; ++mi)
#pragma unroll
        for (int ni = 0; ni < 8; ++ni) {
            float* d = acc[mi * 8 + ni];
            int f = f0 + ni * 8 + 2 * tig;
            int n = n0 + mi * 16 + gid;
            float bb0 = b1s[f], bb1 = b1s[f + 1];
            float2 v0 = make_float2(tf32r(ssp(d[0] + bb0)), tf32r(ssp(d[1] + bb1)));
            float2 v1 = make_float2(tf32r(ssp(d[2] + bb0)), tf32r(ssp(d[3] + bb1)));
            *(float2*)&h_s[n * HS + f]       = v0;
            *(float2*)&h_s[(n + 8) * HS + f] = v1;
        }
    __syncthreads();

    // ================= GEMM2: K=128 (16 k-steps) =================
#pragma unroll
    for (int t = 0; t < 16; ++t) { acc[t][0]=acc[t][1]=acc[t][2]=acc[t][3]=0.f; }

    {
        const uint32_t* h_u = (const uint32_t*)h_s;
        const float4*   wv  = (const float4*)g_Wf2v;
#pragma unroll
        for (int ks = 0; ks < 16; ++ks) {
            const int k0 = ks * 8;
            uint32_t a[2][4];
#pragma unroll
            for (int mi = 0; mi < 2; ++mi) {
                int r = (n0 + mi * 16 + gid) * HS + k0 + tig;
                a[mi][0] = h_u[r];
                a[mi][1] = h_u[r + 8 * HS];
                a[mi][2] = h_u[r + 4];
                a[mi][3] = h_u[r + 8 * HS + 4];
            }
            int r0i = ((k0 + tig)     * F_DIM + f0 + gid * 8) >> 2;
            int r1i = ((k0 + tig + 4) * F_DIM + f0 + gid * 8) >> 2;
            float4 q0 = __ldg(wv + r0i), q1 = __ldg(wv + r0i + 1);
            float4 s0 = __ldg(wv + r1i), s1 = __ldg(wv + r1i + 1);
            uint32_t bq[8] = {__float_as_uint(q0.x),__float_as_uint(q0.y),__float_as_uint(q0.z),__float_as_uint(q0.w),
                              __float_as_uint(q1.x),__float_as_uint(q1.y),__float_as_uint(q1.z),__float_as_uint(q1.w)};
            uint32_t bs[8] = {__float_as_uint(s0.x),__float_as_uint(s0.y),__float_as_uint(s0.z),__float_as_uint(s0.w),
                              __float_as_uint(s1.x),__float_as_uint(s1.y),__float_as_uint(s1.z),__float_as_uint(s1.w)};
#pragma unroll
            for (int ni = 0; ni < 8; ++ni) {
                mma8(acc[0 * 8 + ni], a[0], bq[ni], bs[ni]);
                mma8(acc[1 * 8 + ni], a[1], bq[ni], bs[ni]);
            }
        }
    }
    __syncthreads();   // all warps done reading h before overwrite

    // ---- epi2: Wm = (D2 + b2) * mask -> linear SMEM (reuse h region) ----
#pragma unroll
    for (int mi = 0; mi < 2; ++mi)
#pragma unroll
        for (int ni = 0; ni < 8; ++ni) {
            float* d = acc[mi * 8 + ni];
            int f = f0 + ni * 8 + 2 * tig;
            int n = n0 + mi * 16 + gid;
            float bb0 = b2s[f], bb1 = b2s[f + 1];
            float m0 = msk_sh[n], m1 = msk_sh[n + 8];
            *(float2*)&h_s[n * HS + f]       = make_float2((d[0] + bb0) * m0, (d[1] + bb1) * m0);
            *(float2*)&h_s[(n + 8) * HS + f] = make_float2((d[2] + bb0) * m1, (d[3] + bb1) * m1);
        }
    __syncthreads();

    // ---- reduce: y[atom, f] = sum_n Wm[n,f] * xw[nbr[n], f] ----
    {
        const int at = tid >> 7, f = tid & 127;
        const float* xwb = g_xw + (size_t)b * A_DIM * F_DIM + f;
        float y = 0.0f;
#pragma unroll 8
        for (int j = 0; j < 64; ++j) {
            int n = at * 64 + j;
            float xv = __ldg(xwb + (size_t)nbr_sh[n] * F_DIM);
            y = fmaf(h_s[n * HS + f], xv, y);
        }
        g_y[(size_t)(c * 2 + at) * F_DIM + f] = y;
    }
}

// ---------------------------------------------------------------------------
// Inputs: x, pairwise_mask, neighbors, f_ij, W_f1, b_f1, W_f2, b_f2,
//         W_in2f, W_f2out, b_f2out
// ---------------------------------------------------------------------------
extern "C" void kernel_launch(void* const* d_in, const int* in_sizes, int n_in,
                              void* d_out, int out_size)
{
    const float* x      = (const float*)d_in[0];
    const float* mask   = (const float*)d_in[1];
    const int*   nbrs   = (const int*)  d_in[2];
    const float* f_ij   = (const float*)d_in[3];
    const float* W_f1   = (const float*)d_in[4];
    const float* b_f1   = (const float*)d_in[5];
    const float* W_f2   = (const float*)d_in[6];
    const float* b_f2   = (const float*)d_in[7];
    const float* W_in2f = (const float*)d_in[8];
    const float* W_out  = (const float*)d_in[9];
    const float* b_out  = (const float*)d_in[10];
    float*       out    = (float*)d_out;

    const int BA = in_sizes[0] / F_DIM;   // 8192

    static float* xw_ptr = nullptr;
    static float* y_ptr  = nullptr;
    if (!xw_ptr) { cudaGetSymbolAddress((void**)&xw_ptr, g_xw);
                   cudaGetSymbolAddress((void**)&y_ptr,  g_y); }

    cudaFuncSetAttribute(cfconv_mma, cudaFuncAttributeMaxDynamicSharedMemorySize, SMEM_TOTAL);

    prep_kernel<<<1, 256>>>(W_f1, W_f2);
    dense_kernel<<<BA / 8, F_DIM>>>(x, W_in2f, nullptr, xw_ptr, 0);     // xw = x @ W_in2f
    cfconv_mma<<<BA / 2, 256, SMEM_TOTAL>>>(f_ij, mask, nbrs, b_f1, b_f2);
    dense_kernel<<<BA / 8, F_DIM>>>(y_ptr, W_out, b_out, out, 1);       // out = ssp(y @ W_out + b)
}

// round 11
// speedup vs baseline: 1.6672x; 1.6672x over previous
#include <cuda_runtime.h>
#include <cuda_fp16.h>
#include <math.h>
#include <cstdint>

// B=8, A=1024, N=64, G=50, F=128
#define A_DIM 1024
#define F_DIM 128
#define G_DIM 50
#define LOG2F_CONST 0.6931471805599453f

// ---------------- device scratch ----------------
__device__ float    g_xw[8 * A_DIM * F_DIM];     // x @ W_in2f  (4 MB)
__device__ float    g_y [8 * A_DIM * F_DIM];     // pre-output  (4 MB)
__device__ uint32_t g_W1h[32 * F_DIM];           // W_f1 half2-packed [kp][f], K padded 64
__device__ uint32_t g_W2h[64 * F_DIM];           // W_f2 half2-packed [kp][f]

__device__ __forceinline__ float ssp(float x) {
    return fmaxf(x, 0.0f) + __logf(1.0f + __expf(-fabsf(x))) - LOG2F_CONST;
}
__device__ __forceinline__ uint32_t pack_h2(float a, float b) {
    __half2 v = __floats2half2_rn(a, b);
    return *reinterpret_cast<uint32_t*>(&v);
}

// m16n8k16 row.col fp16 MMA, fp32 accum. lane: gid=lane>>2, tig=lane&3
//   A (f16x2 regs): a0=(row gid,   k 2tig,2tig+1)   a1=(row gid+8, same)
//                   a2=(row gid,   k 2tig+8,+9)     a3=(row gid+8, same)
//   B: b0=(k 2tig,2tig+1, col gid)  b1=(k 2tig+8,+9, col gid)
//   D: d0=(gid,2tig) d1=(gid,2tig+1) d2=(gid+8,2tig) d3=(gid+8,2tig+1)
__device__ __forceinline__ void mma16(float* d, const uint32_t* a, const uint32_t* b) {
    asm volatile(
        "mma.sync.aligned.m16n8k16.row.col.f32.f16.f16.f32 "
        "{%0,%1,%2,%3}, {%4,%5,%6,%7}, {%8,%9}, {%0,%1,%2,%3};"
        : "+f"(d[0]), "+f"(d[1]), "+f"(d[2]), "+f"(d[3])
        : "r"(a[0]), "r"(a[1]), "r"(a[2]), "r"(a[3]), "r"(b[0]), "r"(b[1]));
}

// ---------------- SMEM layout ----------------
// fij2: [128 rows][36 u32]  (32 k-pairs + pad; 36 ≡ 4 mod 32 -> conflict-free)
// h2  : [128 rows][68 u32]  (64 k-pairs + pad; 68 ≡ 4 mod 32) — aliased with Wm
// Wm  : [128 rows][130 f32] (reduce operand; R7-proven)
#define FS2 36
#define HS2 68
#define WS  130
#define OFF_B1   0
#define OFF_B2   512
#define OFF_NBR  1024
#define OFF_MSK  1536
#define OFF_FIJ  2048                 // 128*36*4 = 18432 -> ends 20480
#define OFF_WM   20480                // 128*130*4 = 66560 (h2 aliased at same base)
#define SMEM_TOTAL 87040

// ---------------------------------------------------------------------------
// prep: pack weights to half2 [k-pair][f], zero-padded (K1 -> 64)
// ---------------------------------------------------------------------------
__global__ void prep_kernel(const float* __restrict__ W_f1, const float* __restrict__ W_f2) {
    int t = threadIdx.x;
    for (int i = t; i < 32 * F_DIM; i += blockDim.x) {
        int kp = i >> 7, col = i & 127;
        float w0 = (2 * kp     < G_DIM) ? W_f1[(2 * kp)     * F_DIM + col] : 0.0f;
        float w1 = (2 * kp + 1 < G_DIM) ? W_f1[(2 * kp + 1) * F_DIM + col] : 0.0f;
        g_W1h[i] = pack_h2(w0, w1);
    }
    for (int i = t; i < 64 * F_DIM; i += blockDim.x) {
        int kp = i >> 7, col = i & 127;
        g_W2h[i] = pack_h2(W_f2[(2 * kp) * F_DIM + col], W_f2[(2 * kp + 1) * F_DIM + col]);
    }
}

// ---------------------------------------------------------------------------
// dense: out[r, o] = (ssp?)(in[r,:] @ W[:,o] + bias)   — 8 rows per CTA
// ---------------------------------------------------------------------------
__global__ __launch_bounds__(F_DIM) void dense_kernel(
    const float* __restrict__ in, const float* __restrict__ W,
    const float* __restrict__ bias, float* __restrict__ outp, int apply_ssp)
{
    __shared__ float xs[8 * F_DIM];
    const int r0 = blockIdx.x * 8, o = threadIdx.x;
#pragma unroll
    for (int r = 0; r < 8; ++r)
        xs[r * F_DIM + o] = in[(size_t)(r0 + r) * F_DIM + o];
    __syncthreads();

    float a[8];
    float bb = bias ? __ldg(&bias[o]) : 0.0f;
#pragma unroll
    for (int r = 0; r < 8; ++r) a[r] = bb;
#pragma unroll 4
    for (int c = 0; c < F_DIM; ++c) {
        float w = __ldg(&W[c * F_DIM + o]);
#pragma unroll
        for (int r = 0; r < 8; ++r)
            a[r] = fmaf(xs[r * F_DIM + c], w, a[r]);
    }
#pragma unroll
    for (int r = 0; r < 8; ++r)
        outp[(size_t)(r0 + r) * F_DIM + o] = apply_ssp ? ssp(a[r]) : a[r];
}

// ---------------------------------------------------------------------------
// Main: one CTA per 2 atoms (128 rows), 256 threads, 8 warps (4M x 2N).
// fp16 m16n8k16: GEMM1 K=64 in 4 k-steps, GEMM2 K=128 in 8 k-steps.
// ---------------------------------------------------------------------------
__global__ __launch_bounds__(256, 2) void cfconv_mma(
    const float* __restrict__ f_ij,   // [B,A,N,G]
    const float* __restrict__ mask,   // [B,A,N]
    const int*   __restrict__ nbrs,   // [B,A,N]
    const float* __restrict__ b_f1,
    const float* __restrict__ b_f2)
{
    extern __shared__ char smem[];
    float*    b1s    = (float*)   (smem + OFF_B1);
    float*    b2s    = (float*)   (smem + OFF_B2);
    int*      nbr_sh = (int*)     (smem + OFF_NBR);
    float*    msk_sh = (float*)   (smem + OFF_MSK);
    uint32_t* fij2   = (uint32_t*)(smem + OFF_FIJ);
    uint32_t* h2     = (uint32_t*)(smem + OFF_WM);   // fp16 h (aliased)
    float*    wm     = (float*)   (smem + OFF_WM);   // fp32 Wm (after GEMM2)

    const int tid = threadIdx.x, wid = tid >> 5, lane = tid & 31;
    const int gid = lane >> 2, tig = lane & 3;
    const int c = blockIdx.x;          // atoms 2c, 2c+1
    const int b = c >> 9;              // batch

    if (tid < 128) {
        b1s[tid]    = b_f1[tid];
        b2s[tid]    = b_f2[tid];
        nbr_sh[tid] = nbrs[(size_t)c * 128 + tid];
        msk_sh[tid] = mask[(size_t)c * 128 + tid];
    }
    // stage f_ij [128 rows][32 k-pairs] as half2, zero-pad k>=50
    {
        const float* fb = f_ij + (size_t)c * 128 * G_DIM;
        for (int i = tid; i < 128 * 32; i += 256) {
            int r = i >> 5, kp = i & 31;
            uint32_t v;
            if (kp < 25) {               // cols 2kp, 2kp+1 both < 50
                float2 p = *(const float2*)(fb + r * G_DIM + 2 * kp);
                v = pack_h2(p.x, p.y);
            } else {
                v = 0u;
            }
            fij2[r * FS2 + kp] = v;
        }
    }
    __syncthreads();

    const int n0 = (wid & 3) * 32;     // warp's 32 rows
    const int f0 = (wid >> 2) * 64;    // warp's 64 cols

    // ================= GEMM1: K=64 (4 k-steps of 16) =================
    float acc[16][4];
#pragma unroll
    for (int t = 0; t < 16; ++t) { acc[t][0]=acc[t][1]=acc[t][2]=acc[t][3]=0.f; }

#pragma unroll
    for (int ks = 0; ks < 4; ++ks) {
        const int kq = ks * 8;         // k-pair base
        uint32_t a[2][4], bf[8][2];
#pragma unroll
        for (int mi = 0; mi < 2; ++mi) {
            int r = (n0 + mi * 16 + gid) * FS2 + kq + tig;
            a[mi][0] = fij2[r];
            a[mi][1] = fij2[r + 8 * FS2];
            a[mi][2] = fij2[r + 4];
            a[mi][3] = fij2[r + 8 * FS2 + 4];
        }
#pragma unroll
        for (int ni = 0; ni < 8; ++ni) {
            int col = f0 + ni * 8 + gid;
            bf[ni][0] = __ldg(&g_W1h[(kq + tig)     * F_DIM + col]);
            bf[ni][1] = __ldg(&g_W1h[(kq + tig + 4) * F_DIM + col]);
        }
#pragma unroll
        for (int mi = 0; mi < 2; ++mi)
#pragma unroll
            for (int ni = 0; ni < 8; ++ni)
                mma16(acc[mi * 8 + ni], a[mi], bf[ni]);
    }

    // ---- epi1: h = fp16(ssp(D1 + b1)) -> half2 SMEM [n][kp] ----
#pragma unroll
    for (int mi = 0; mi < 2; ++mi)
#pragma unroll
        for (int ni = 0; ni < 8; ++ni) {
            float* d = acc[mi * 8 + ni];
            int f = f0 + ni * 8 + 2 * tig;
            int n = n0 + mi * 16 + gid;
            int kp = (f >> 1);                       // = f0/2 + ni*4 + tig
            float bb0 = b1s[f], bb1 = b1s[f + 1];
            h2[n * HS2 + kp]       = pack_h2(ssp(d[0] + bb0), ssp(d[1] + bb1));
            h2[(n + 8) * HS2 + kp] = pack_h2(ssp(d[2] + bb0), ssp(d[3] + bb1));
        }
    __syncthreads();

    // ================= GEMM2: K=128 (8 k-steps of 16) =================
#pragma unroll
    for (int t = 0; t < 16; ++t) { acc[t][0]=acc[t][1]=acc[t][2]=acc[t][3]=0.f; }

#pragma unroll
    for (int ks = 0; ks < 8; ++ks) {
        const int kq = ks * 8;
        uint32_t a[2][4], bf[8][2];
#pragma unroll
        for (int mi = 0; mi < 2; ++mi) {
            int r = (n0 + mi * 16 + gid) * HS2 + kq + tig;
            a[mi][0] = h2[r];
            a[mi][1] = h2[r + 8 * HS2];
            a[mi][2] = h2[r + 4];
            a[mi][3] = h2[r + 8 * HS2 + 4];
        }
#pragma unroll
        for (int ni = 0; ni < 8; ++ni) {
            int col = f0 + ni * 8 + gid;
            bf[ni][0] = __ldg(&g_W2h[(kq + tig)     * F_DIM + col]);
            bf[ni][1] = __ldg(&g_W2h[(kq + tig + 4) * F_DIM + col]);
        }
#pragma unroll
        for (int mi = 0; mi < 2; ++mi)
#pragma unroll
            for (int ni = 0; ni < 8; ++ni)
                mma16(acc[mi * 8 + ni], a[mi], bf[ni]);
    }
    __syncthreads();   // all warps done reading h2 before Wm overwrite

    // ---- epi2: Wm = (D2 + b2) * mask -> fp32 SMEM [128][WS] ----
#pragma unroll
    for (int mi = 0; mi < 2; ++mi)
#pragma unroll
        for (int ni = 0; ni < 8; ++ni) {
            float* d = acc[mi * 8 + ni];
            int f = f0 + ni * 8 + 2 * tig;
            int n = n0 + mi * 16 + gid;
            float bb0 = b2s[f], bb1 = b2s[f + 1];
            float m0 = msk_sh[n], m1 = msk_sh[n + 8];
            *(float2*)&wm[n * WS + f]       = make_float2((d[0] + bb0) * m0, (d[1] + bb1) * m0);
            *(float2*)&wm[(n + 8) * WS + f] = make_float2((d[2] + bb0) * m1, (d[3] + bb1) * m1);
        }
    __syncthreads();

    // ---- reduce: y[atom, f] = sum_n Wm[n,f] * xw[nbr[n], f] ----
    {
        const int at = tid >> 7, f = tid & 127;
        const float* xwb = g_xw + (size_t)b * A_DIM * F_DIM + f;
        float y = 0.0f;
#pragma unroll 8
        for (int j = 0; j < 64; ++j) {
            int n = at * 64 + j;
            float xv = __ldg(xwb + (size_t)nbr_sh[n] * F_DIM);
            y = fmaf(wm[n * WS + f], xv, y);
        }
        g_y[(size_t)(c * 2 + at) * F_DIM + f] = y;
    }
}

// ---------------------------------------------------------------------------
// Inputs: x, pairwise_mask, neighbors, f_ij, W_f1, b_f1, W_f2, b_f2,
//         W_in2f, W_f2out, b_f2out
// ---------------------------------------------------------------------------
extern "C" void kernel_launch(void* const* d_in, const int* in_sizes, int n_in,
                              void* d_out, int out_size)
{
    const float* x      = (const float*)d_in[0];
    const float* mask   = (const float*)d_in[1];
    const int*   nbrs   = (const int*)  d_in[2];
    const float* f_ij   = (const float*)d_in[3];
    const float* W_f1   = (const float*)d_in[4];
    const float* b_f1   = (const float*)d_in[5];
    const float* W_f2   = (const float*)d_in[6];
    const float* b_f2   = (const float*)d_in[7];
    const float* W_in2f = (const float*)d_in[8];
    const float* W_out  = (const float*)d_in[9];
    const float* b_out  = (const float*)d_in[10];
    float*       out    = (float*)d_out;

    const int BA = in_sizes[0] / F_DIM;   // 8192

    static float* xw_ptr = nullptr;
    static float* y_ptr  = nullptr;
    if (!xw_ptr) { cudaGetSymbolAddress((void**)&xw_ptr, g_xw);
                   cudaGetSymbolAddress((void**)&y_ptr,  g_y); }

    cudaFuncSetAttribute(cfconv_mma, cudaFuncAttributeMaxDynamicSharedMemorySize, SMEM_TOTAL);

    prep_kernel<<<1, 256>>>(W_f1, W_f2);
    dense_kernel<<<BA / 8, F_DIM>>>(x, W_in2f, nullptr, xw_ptr, 0);     // xw = x @ W_in2f
    cfconv_mma<<<BA / 2, 256, SMEM_TOTAL>>>(f_ij, mask, nbrs, b_f1, b_f2);
    dense_kernel<<<BA / 8, F_DIM>>>(y_ptr, W_out, b_out, out, 1);       // out = ssp(y @ W_out + b)
}

// round 12
// speedup vs baseline: 1.9044x; 1.1422x over previous
#include <cuda_runtime.h>
#include <cuda_fp16.h>
#include <math.h>
#include <cstdint>

// B=8, A=1024, N=64, G=50, F=128
#define A_DIM 1024
#define F_DIM 128
#define G_DIM 50
#define PAIRS 4096
#define LOG2F_CONST 0.6931471805599453f

// ---------------- device scratch ----------------
__device__ float    g_xw[8 * A_DIM * F_DIM];     // x @ W_in2f  (4 MB)
__device__ float    g_y [8 * A_DIM * F_DIM];     // pre-output  (4 MB)
__device__ uint32_t g_W1h[32 * F_DIM];           // W_f1 half2 [kp][f], K padded 64
__device__ uint32_t g_W2h[64 * F_DIM];           // W_f2 half2 [kp][f]

__device__ __forceinline__ float ssp(float x) {
    return fmaxf(x, 0.0f) + __logf(1.0f + __expf(-fabsf(x))) - LOG2F_CONST;
}
__device__ __forceinline__ uint32_t pack_h2(float a, float b) {
    __half2 v = __floats2half2_rn(a, b);
    return *reinterpret_cast<uint32_t*>(&v);
}
__device__ __forceinline__ uint32_t smem_u32(const void* p) {
    uint32_t a;
    asm("{ .reg .u64 t; cvta.to.shared.u64 t, %1; cvt.u32.u64 %0, t; }" : "=r"(a) : "l"(p));
    return a;
}
__device__ __forceinline__ void cp8(uint32_t dst, const void* src) {
    asm volatile("cp.async.ca.shared.global [%0], [%1], 8;" :: "r"(dst), "l"(src) : "memory");
}

// m16n8k16 row.col fp16 MMA, fp32 accum. lane: gid=lane>>2, tig=lane&3
__device__ __forceinline__ void mma16(float* d, const uint32_t* a, const uint32_t* b) {
    asm volatile(
        "mma.sync.aligned.m16n8k16.row.col.f32.f16.f16.f32 "
        "{%0,%1,%2,%3}, {%4,%5,%6,%7}, {%8,%9}, {%0,%1,%2,%3};"
        : "+f"(d[0]), "+f"(d[1]), "+f"(d[2]), "+f"(d[3])
        : "r"(a[0]), "r"(a[1]), "r"(a[2]), "r"(a[3]), "r"(b[0]), "r"(b[1]));
}

// ---------------- SMEM layout ----------------
// raw : 2 x [128 rows][68 f32]  (fp32 f_ij, cols 50..67 zero)  stride 68 -> ~conflict-free
// h2  : [128 rows][68 u32]      (fp16 h)  — wm [64][130] f32 aliased after GEMM2
#define RS   68
#define HS2  68
#define WS   130
#define OFF_B1   0
#define OFF_B2   512
#define OFF_NBR  1024      // 2 x 128 int
#define OFF_MSK  2048      // 2 x 128 f32
#define OFF_Y    3072      // 256 f32
#define OFF_RAW  4096      // 2 x 34816 = 69632
#define OFF_H    73728     // 34816 (h2; wm 33280 aliased)
#define SMEM_TOTAL 108544

// ---------------------------------------------------------------------------
// prep: pack weights to half2 [k-pair][f], zero-padded
// ---------------------------------------------------------------------------
__global__ void prep_kernel(const float* __restrict__ W_f1, const float* __restrict__ W_f2) {
    int t = threadIdx.x;
    for (int i = t; i < 32 * F_DIM; i += blockDim.x) {
        int kp = i >> 7, col = i & 127;
        float w0 = (2 * kp     < G_DIM) ? W_f1[(2 * kp)     * F_DIM + col] : 0.0f;
        float w1 = (2 * kp + 1 < G_DIM) ? W_f1[(2 * kp + 1) * F_DIM + col] : 0.0f;
        g_W1h[i] = pack_h2(w0, w1);
    }
    for (int i = t; i < 64 * F_DIM; i += blockDim.x) {
        int kp = i >> 7, col = i & 127;
        g_W2h[i] = pack_h2(W_f2[(2 * kp) * F_DIM + col], W_f2[(2 * kp + 1) * F_DIM + col]);
    }
}

// ---------------------------------------------------------------------------
// dense: out[r, o] = (ssp?)(in[r,:] @ W[:,o] + bias)   — 8 rows per CTA
// ---------------------------------------------------------------------------
__global__ __launch_bounds__(F_DIM) void dense_kernel(
    const float* __restrict__ in, const float* __restrict__ W,
    const float* __restrict__ bias, float* __restrict__ outp, int apply_ssp)
{
    __shared__ float xs[8 * F_DIM];
    const int r0 = blockIdx.x * 8, o = threadIdx.x;
#pragma unroll
    for (int r = 0; r < 8; ++r)
        xs[r * F_DIM + o] = in[(size_t)(r0 + r) * F_DIM + o];
    __syncthreads();

    float a[8];
    float bb = bias ? __ldg(&bias[o]) : 0.0f;
#pragma unroll
    for (int r = 0; r < 8; ++r) a[r] = bb;
#pragma unroll 4
    for (int c = 0; c < F_DIM; ++c) {
        float w = __ldg(&W[c * F_DIM + o]);
#pragma unroll
        for (int r = 0; r < 8; ++r)
            a[r] = fmaf(xs[r * F_DIM + c], w, a[r]);
    }
#pragma unroll
    for (int r = 0; r < 8; ++r)
        outp[(size_t)(r0 + r) * F_DIM + o] = apply_ssp ? ssp(a[r]) : a[r];
}

// ---------------------------------------------------------------------------
// Persistent main: grid = 2*SMs, each CTA loops over atom-pairs with
// cp.async double-buffered staging of raw f_ij (+nbr/mask).
// ---------------------------------------------------------------------------
__global__ __launch_bounds__(256, 2) void cfconv_mma(
    const float* __restrict__ f_ij,   // [B,A,N,G]
    const float* __restrict__ mask,   // [B,A,N]
    const int*   __restrict__ nbrs,   // [B,A,N]
    const float* __restrict__ b_f1,
    const float* __restrict__ b_f2)
{
    extern __shared__ char smem[];
    float*    b1s  = (float*)(smem + OFF_B1);
    float*    b2s  = (float*)(smem + OFF_B2);
    float*    y_sh = (float*)(smem + OFF_Y);
    float*    rawb = (float*)(smem + OFF_RAW);
    uint32_t* h2   = (uint32_t*)(smem + OFF_H);
    float*    wm   = (float*)(smem + OFF_H);       // aliased after GEMM2

    const int tid = threadIdx.x, wid = tid >> 5, lane = tid & 31;
    const int gid = lane >> 2, tig = lane & 3;
    const uint32_t sb = smem_u32(smem);

    // zero raw buffers (pad cols survive; cp.async overwrites cols 0..49)
    for (int i = tid; i < 2 * 128 * RS; i += 256) rawb[i] = 0.0f;
    if (tid < 128) { b1s[tid] = b_f1[tid]; b2s[tid] = b_f2[tid]; }
    __syncthreads();

    // staging helper (inlined twice below):
    //   f_ij rows: thread t -> row t>>1, chunks of 8B; nbr/mask via first 128 threads
    const int srow = tid >> 1;
    const int sc0  = (tid & 1) ? 13 : 0;
    const int snch = (tid & 1) ? 12 : 13;

    int p = blockIdx.x;
    if (p < PAIRS) {
        const float* src = f_ij + (size_t)p * 6400 + srow * 50 + sc0 * 2;
        uint32_t dst = sb + OFF_RAW + (srow * RS + sc0 * 2) * 4;
        for (int cch = 0; cch < snch; ++cch) cp8(dst + cch * 8, src + cch * 2);
        if (tid < 64)        cp8(sb + OFF_NBR + tid * 8, nbrs + (size_t)p * 128 + tid * 2);
        else if (tid < 128)  cp8(sb + OFF_MSK + (tid - 64) * 8, mask + (size_t)p * 128 + (tid - 64) * 2);
        asm volatile("cp.async.commit_group;" ::: "memory");
    }

    const int n0 = (wid & 3) * 32;     // warp's 32 rows
    const int f0 = (wid >> 2) * 64;    // warp's 64 cols
    int buf = 0;

    for (; p < PAIRS; p += gridDim.x) {
        asm volatile("cp.async.wait_group 0;" ::: "memory");
        __syncthreads();

        // prefetch next pair into the other buffer (overlaps all compute below)
        int pn = p + gridDim.x;
        if (pn < PAIRS) {
            int nb = buf ^ 1;
            const float* src = f_ij + (size_t)pn * 6400 + srow * 50 + sc0 * 2;
            uint32_t dst = sb + OFF_RAW + (nb * 128 * RS + srow * RS + sc0 * 2) * 4;
            for (int cch = 0; cch < snch; ++cch) cp8(dst + cch * 8, src + cch * 2);
            if (tid < 64)        cp8(sb + OFF_NBR + nb * 512 + tid * 8, nbrs + (size_t)pn * 128 + tid * 2);
            else if (tid < 128)  cp8(sb + OFF_MSK + nb * 512 + (tid - 64) * 8, mask + (size_t)pn * 128 + (tid - 64) * 2);
            asm volatile("cp.async.commit_group;" ::: "memory");
        }

        const float* raw   = rawb + buf * 128 * RS;
        const int*   nbr_c = (const int*)(smem + OFF_NBR) + buf * 128;
        const float* msk_c = (const float*)(smem + OFF_MSK) + buf * 128;
        const int    b     = p >> 9;   // batch

        // ================= GEMM1: K=64 (4 k-steps of 16), on-the-fly cvt ====
        float acc[16][4];
#pragma unroll
        for (int t = 0; t < 16; ++t) { acc[t][0]=acc[t][1]=acc[t][2]=acc[t][3]=0.f; }

#pragma unroll
        for (int ks = 0; ks < 4; ++ks) {
            const int k0 = ks * 16;        // float col base
            const int kq = ks * 8;         // k-pair base (weights)
            uint32_t a[2][4], bf[8][2];
#pragma unroll
            for (int mi = 0; mi < 2; ++mi) {
                const float* r0p = raw + (n0 + mi * 16 + gid) * RS + k0 + 2 * tig;
                const float* r1p = r0p + 8 * RS;
                float2 v0 = *(const float2*)r0p;
                float2 v1 = *(const float2*)r1p;
                float2 v2 = *(const float2*)(r0p + 8);
                float2 v3 = *(const float2*)(r1p + 8);
                a[mi][0] = pack_h2(v0.x, v0.y);
                a[mi][1] = pack_h2(v1.x, v1.y);
                a[mi][2] = pack_h2(v2.x, v2.y);
                a[mi][3] = pack_h2(v3.x, v3.y);
            }
#pragma unroll
            for (int ni = 0; ni < 8; ++ni) {
                int col = f0 + ni * 8 + gid;
                bf[ni][0] = __ldg(&g_W1h[(kq + tig)     * F_DIM + col]);
                bf[ni][1] = __ldg(&g_W1h[(kq + tig + 4) * F_DIM + col]);
            }
#pragma unroll
            for (int mi = 0; mi < 2; ++mi)
#pragma unroll
                for (int ni = 0; ni < 8; ++ni)
                    mma16(acc[mi * 8 + ni], a[mi], bf[ni]);
        }

        // ---- epi1: h = fp16(ssp(D1 + b1)) -> half2 SMEM ----
#pragma unroll
        for (int mi = 0; mi < 2; ++mi)
#pragma unroll
            for (int ni = 0; ni < 8; ++ni) {
                float* d = acc[mi * 8 + ni];
                int f = f0 + ni * 8 + 2 * tig;
                int n = n0 + mi * 16 + gid;
                int kp = f >> 1;
                float bb0 = b1s[f], bb1 = b1s[f + 1];
                h2[n * HS2 + kp]       = pack_h2(ssp(d[0] + bb0), ssp(d[1] + bb1));
                h2[(n + 8) * HS2 + kp] = pack_h2(ssp(d[2] + bb0), ssp(d[3] + bb1));
            }
        __syncthreads();

        // ================= GEMM2: K=128 (8 k-steps of 16) =================
#pragma unroll
        for (int t = 0; t < 16; ++t) { acc[t][0]=acc[t][1]=acc[t][2]=acc[t][3]=0.f; }

#pragma unroll
        for (int ks = 0; ks < 8; ++ks) {
            const int kq = ks * 8;
            uint32_t a[2][4], bf[8][2];
#pragma unroll
            for (int mi = 0; mi < 2; ++mi) {
                int r = (n0 + mi * 16 + gid) * HS2 + kq + tig;
                a[mi][0] = h2[r];
                a[mi][1] = h2[r + 8 * HS2];
                a[mi][2] = h2[r + 4];
                a[mi][3] = h2[r + 8 * HS2 + 4];
            }
#pragma unroll
            for (int ni = 0; ni < 8; ++ni) {
                int col = f0 + ni * 8 + gid;
                bf[ni][0] = __ldg(&g_W2h[(kq + tig)     * F_DIM + col]);
                bf[ni][1] = __ldg(&g_W2h[(kq + tig + 4) * F_DIM + col]);
            }
#pragma unroll
            for (int mi = 0; mi < 2; ++mi)
#pragma unroll
                for (int ni = 0; ni < 8; ++ni)
                    mma16(acc[mi * 8 + ni], a[mi], bf[ni]);
        }
        __syncthreads();   // h2 reads done; wm may overwrite

        // ---- two-phase epilogue+reduce (wm [64][130] aliased over h2) ----
        const float* xwb = g_xw + (size_t)b * A_DIM * F_DIM;

        // phase A: atom0 (rows 0..63) — warps with (wid&3) in {0,1}
        if ((wid & 3) < 2) {
#pragma unroll
            for (int mi = 0; mi < 2; ++mi)
#pragma unroll
                for (int ni = 0; ni < 8; ++ni) {
                    float* d = acc[mi * 8 + ni];
                    int f = f0 + ni * 8 + 2 * tig;
                    int n = n0 + mi * 16 + gid;
                    float bb0 = b2s[f], bb1 = b2s[f + 1];
                    float m0 = msk_c[n], m1 = msk_c[n + 8];
                    *(float2*)&wm[n * WS + f]       = make_float2((d[0] + bb0) * m0, (d[1] + bb1) * m0);
                    *(float2*)&wm[(n + 8) * WS + f] = make_float2((d[2] + bb0) * m1, (d[3] + bb1) * m1);
                }
        }
        __syncthreads();
        {
            const int half = tid >> 7, f = tid & 127;
            float y = 0.0f;
#pragma unroll 8
            for (int j = 0; j < 32; ++j) {
                int n = half * 32 + j;
                float xv = __ldg(xwb + (size_t)nbr_c[n] * F_DIM + f);
                y = fmaf(wm[n * WS + f], xv, y);
            }
            y_sh[half * 128 + f] = y;
        }
        __syncthreads();
        if (tid < 128)
            g_y[(size_t)(p * 2) * F_DIM + tid] = y_sh[tid] + y_sh[128 + tid];

        // phase B: atom1 (rows 64..127) — warps with (wid&3) in {2,3}
        if ((wid & 3) >= 2) {
#pragma unroll
            for (int mi = 0; mi < 2; ++mi)
#pragma unroll
                for (int ni = 0; ni < 8; ++ni) {
                    float* d = acc[mi * 8 + ni];
                    int f = f0 + ni * 8 + 2 * tig;
                    int n = n0 + mi * 16 + gid;        // 64..127
                    int nl = n - 64;
                    float bb0 = b2s[f], bb1 = b2s[f + 1];
                    float m0 = msk_c[n], m1 = msk_c[n + 8];
                    *(float2*)&wm[nl * WS + f]       = make_float2((d[0] + bb0) * m0, (d[1] + bb1) * m0);
                    *(float2*)&wm[(nl + 8) * WS + f] = make_float2((d[2] + bb0) * m1, (d[3] + bb1) * m1);
                }
        }
        __syncthreads();
        {
            const int half = tid >> 7, f = tid & 127;
            float y = 0.0f;
#pragma unroll 8
            for (int j = 0; j < 32; ++j) {
                int nl = half * 32 + j;
                float xv = __ldg(xwb + (size_t)nbr_c[64 + nl] * F_DIM + f);
                y = fmaf(wm[nl * WS + f], xv, y);
            }
            y_sh[half * 128 + f] = y;
        }
        __syncthreads();
        if (tid < 128)
            g_y[(size_t)(p * 2 + 1) * F_DIM + tid] = y_sh[tid] + y_sh[128 + tid];

        buf ^= 1;
    }
}

// ---------------------------------------------------------------------------
// Inputs: x, pairwise_mask, neighbors, f_ij, W_f1, b_f1, W_f2, b_f2,
//         W_in2f, W_f2out, b_f2out
// ---------------------------------------------------------------------------
extern "C" void kernel_launch(void* const* d_in, const int* in_sizes, int n_in,
                              void* d_out, int out_size)
{
    const float* x      = (const float*)d_in[0];
    const float* mask   = (const float*)d_in[1];
    const int*   nbrs   = (const int*)  d_in[2];
    const float* f_ij   = (const float*)d_in[3];
    const float* W_f1   = (const float*)d_in[4];
    const float* b_f1   = (const float*)d_in[5];
    const float* W_f2   = (const float*)d_in[6];
    const float* b_f2   = (const float*)d_in[7];
    const float* W_in2f = (const float*)d_in[8];
    const float* W_out  = (const float*)d_in[9];
    const float* b_out  = (const float*)d_in[10];
    float*       out    = (float*)d_out;

    const int BA = in_sizes[0] / F_DIM;   // 8192

    static float* xw_ptr = nullptr;
    static float* y_ptr  = nullptr;
    static int    nsm    = 0;
    if (!xw_ptr) {
        cudaGetSymbolAddress((void**)&xw_ptr, g_xw);
        cudaGetSymbolAddress((void**)&y_ptr,  g_y);
        cudaDeviceGetAttribute(&nsm, cudaDevAttrMultiProcessorCount, 0);
        cudaFuncSetAttribute(cfconv_mma, cudaFuncAttributeMaxDynamicSharedMemorySize, SMEM_TOTAL);
    }

    prep_kernel<<<1, 256>>>(W_f1, W_f2);
    dense_kernel<<<BA / 8, F_DIM>>>(x, W_in2f, nullptr, xw_ptr, 0);     // xw = x @ W_in2f
    cfconv_mma<<<2 * nsm, 256, SMEM_TOTAL>>>(f_ij, mask, nbrs, b_f1, b_f2);
    dense_kernel<<<BA / 8, F_DIM>>>(y_ptr, W_out, b_out, out, 1);       // out = ssp(y @ W_out + b)
}

// round 13
// speedup vs baseline: 1.9854x; 1.0425x over previous
#include <cuda_runtime.h>
#include <cuda_fp16.h>
#include <math.h>
#include <cstdint>

// B=8, A=1024, N=64, G=50, F=128
#define A_DIM 1024
#define F_DIM 128
#define G_DIM 50
#define PAIRS 4096
#define LOG2F_CONST 0.6931471805599453f

// ---------------- device scratch ----------------
__device__ float    g_xw[8 * A_DIM * F_DIM];     // x @ W_in2f  (4 MB)
__device__ float    g_y [8 * A_DIM * F_DIM];     // pre-output  (4 MB)
__device__ uint32_t g_W1h[32 * F_DIM];           // W_f1 half2 [kp][f], K padded 64
__device__ uint32_t g_W2h[64 * F_DIM];           // W_f2 half2 [kp][f]

__device__ __forceinline__ float ssp(float x) {
    return fmaxf(x, 0.0f) + __logf(1.0f + __expf(-fabsf(x))) - LOG2F_CONST;
}
__device__ __forceinline__ uint32_t pack_h2(float a, float b) {
    __half2 v = __floats2half2_rn(a, b);
    return *reinterpret_cast<uint32_t*>(&v);
}
__device__ __forceinline__ uint32_t smem_u32(const void* p) {
    uint32_t a;
    asm("{ .reg .u64 t; cvta.to.shared.u64 t, %1; cvt.u32.u64 %0, t; }" : "=r"(a) : "l"(p));
    return a;
}
__device__ __forceinline__ void cp8(uint32_t dst, const void* src) {
    asm volatile("cp.async.ca.shared.global [%0], [%1], 8;" :: "r"(dst), "l"(src) : "memory");
}

// m16n8k16 row.col fp16 MMA, fp32 accum. lane: gid=lane>>2, tig=lane&3
__device__ __forceinline__ void mma16(float* d, const uint32_t* a, const uint32_t* b) {
    asm volatile(
        "mma.sync.aligned.m16n8k16.row.col.f32.f16.f16.f32 "
        "{%0,%1,%2,%3}, {%4,%5,%6,%7}, {%8,%9}, {%0,%1,%2,%3};"
        : "+f"(d[0]), "+f"(d[1]), "+f"(d[2]), "+f"(d[3])
        : "r"(a[0]), "r"(a[1]), "r"(a[2]), "r"(a[3]), "r"(b[0]), "r"(b[1]));
}

// ---------------- SMEM layout ----------------
// raw : 2 x [128 rows][68 f32]  (fp32 f_ij, cols 50..67 zero)
// h2  : [128 rows][68 u32]      (fp16 h, then fp16 Wm — full 128 rows fit)
#define RS   68
#define HS2  68
#define OFF_B1   0
#define OFF_B2   512
#define OFF_NBR  1024      // 2 x 128 int
#define OFF_MSK  2048      // 2 x 128 f32
#define OFF_RAW  4096      // 2 x 34816 = 69632
#define OFF_H    73728     // 34816
#define SMEM_TOTAL 108544

// ---------------------------------------------------------------------------
// prep: pack weights to half2 [k-pair][f], zero-padded
// ---------------------------------------------------------------------------
__global__ void prep_kernel(const float* __restrict__ W_f1, const float* __restrict__ W_f2) {
    int t = threadIdx.x;
    for (int i = t; i < 32 * F_DIM; i += blockDim.x) {
        int kp = i >> 7, col = i & 127;
        float w0 = (2 * kp     < G_DIM) ? W_f1[(2 * kp)     * F_DIM + col] : 0.0f;
        float w1 = (2 * kp + 1 < G_DIM) ? W_f1[(2 * kp + 1) * F_DIM + col] : 0.0f;
        g_W1h[i] = pack_h2(w0, w1);
    }
    for (int i = t; i < 64 * F_DIM; i += blockDim.x) {
        int kp = i >> 7, col = i & 127;
        g_W2h[i] = pack_h2(W_f2[(2 * kp) * F_DIM + col], W_f2[(2 * kp + 1) * F_DIM + col]);
    }
}

// ---------------------------------------------------------------------------
// dense: out[r, o] = (ssp?)(in[r,:] @ W[:,o] + bias)   — 16 rows per CTA
// ---------------------------------------------------------------------------
__global__ __launch_bounds__(F_DIM) void dense_kernel(
    const float* __restrict__ in, const float* __restrict__ W,
    const float* __restrict__ bias, float* __restrict__ outp, int apply_ssp)
{
    __shared__ float xs[16 * F_DIM];
    const int r0 = blockIdx.x * 16, o = threadIdx.x;
#pragma unroll
    for (int r = 0; r < 16; ++r)
        xs[r * F_DIM + o] = in[(size_t)(r0 + r) * F_DIM + o];
    __syncthreads();

    float a[16];
    float bb = bias ? __ldg(&bias[o]) : 0.0f;
#pragma unroll
    for (int r = 0; r < 16; ++r) a[r] = bb;
#pragma unroll 4
    for (int c = 0; c < F_DIM; ++c) {
        float w = __ldg(&W[c * F_DIM + o]);
#pragma unroll
        for (int r = 0; r < 16; ++r)
            a[r] = fmaf(xs[r * F_DIM + c], w, a[r]);
    }
#pragma unroll
    for (int r = 0; r < 16; ++r)
        outp[(size_t)(r0 + r) * F_DIM + o] = apply_ssp ? ssp(a[r]) : a[r];
}

// ---------------------------------------------------------------------------
// Persistent main: grid = 2*SMs, cp.async double-buffered raw f_ij staging,
// fp16 Wm epilogue (single phase, 4 syncs/pair).
// ---------------------------------------------------------------------------
__global__ __launch_bounds__(256, 2) void cfconv_mma(
    const float* __restrict__ f_ij,   // [B,A,N,G]
    const float* __restrict__ mask,   // [B,A,N]
    const int*   __restrict__ nbrs,   // [B,A,N]
    const float* __restrict__ b_f1,
    const float* __restrict__ b_f2)
{
    extern __shared__ char smem[];
    float*    b1s  = (float*)(smem + OFF_B1);
    float*    b2s  = (float*)(smem + OFF_B2);
    float*    rawb = (float*)(smem + OFF_RAW);
    uint32_t* h2   = (uint32_t*)(smem + OFF_H);

    const int tid = threadIdx.x, wid = tid >> 5, lane = tid & 31;
    const int gid = lane >> 2, tig = lane & 3;
    const uint32_t sb = smem_u32(smem);

    // zero raw buffers (pad cols survive; cp.async overwrites cols 0..49)
    for (int i = tid; i < 2 * 128 * RS; i += 256) rawb[i] = 0.0f;
    if (tid < 128) { b1s[tid] = b_f1[tid]; b2s[tid] = b_f2[tid]; }
    __syncthreads();

    // staging mapping: thread t -> row t>>1, 8B chunks over 50 floats
    const int srow = tid >> 1;
    const int sc0  = (tid & 1) ? 13 : 0;
    const int snch = (tid & 1) ? 12 : 13;

    int p = blockIdx.x;
    if (p < PAIRS) {
        const float* src = f_ij + (size_t)p * 6400 + srow * 50 + sc0 * 2;
        uint32_t dst = sb + OFF_RAW + (srow * RS + sc0 * 2) * 4;
        for (int cch = 0; cch < snch; ++cch) cp8(dst + cch * 8, src + cch * 2);
        if (tid < 64)        cp8(sb + OFF_NBR + tid * 8, nbrs + (size_t)p * 128 + tid * 2);
        else if (tid < 128)  cp8(sb + OFF_MSK + (tid - 64) * 8, mask + (size_t)p * 128 + (tid - 64) * 2);
        asm volatile("cp.async.commit_group;" ::: "memory");
    }

    const int n0 = (wid & 3) * 32;     // warp's 32 rows
    const int f0 = (wid >> 2) * 64;    // warp's 64 cols
    int buf = 0;

    for (; p < PAIRS; p += gridDim.x) {
        asm volatile("cp.async.wait_group 0;" ::: "memory");
        __syncthreads();               // sync 1: staged data ready; prev reduce done

        // prefetch next pair into the other buffer
        int pn = p + gridDim.x;
        if (pn < PAIRS) {
            int nb = buf ^ 1;
            const float* src = f_ij + (size_t)pn * 6400 + srow * 50 + sc0 * 2;
            uint32_t dst = sb + OFF_RAW + (nb * 128 * RS + srow * RS + sc0 * 2) * 4;
            for (int cch = 0; cch < snch; ++cch) cp8(dst + cch * 8, src + cch * 2);
            if (tid < 64)        cp8(sb + OFF_NBR + nb * 512 + tid * 8, nbrs + (size_t)pn * 128 + tid * 2);
            else if (tid < 128)  cp8(sb + OFF_MSK + nb * 512 + (tid - 64) * 8, mask + (size_t)pn * 128 + (tid - 64) * 2);
            asm volatile("cp.async.commit_group;" ::: "memory");
        }

        const float* raw   = rawb + buf * 128 * RS;
        const int*   nbr_c = (const int*)(smem + OFF_NBR) + buf * 128;
        const float* msk_c = (const float*)(smem + OFF_MSK) + buf * 128;
        const int    b     = p >> 9;   // batch

        // ================= GEMM1: K=64 (4 k-steps of 16), on-the-fly cvt ====
        float acc[16][4];
#pragma unroll
        for (int t = 0; t < 16; ++t) { acc[t][0]=acc[t][1]=acc[t][2]=acc[t][3]=0.f; }

#pragma unroll
        for (int ks = 0; ks < 4; ++ks) {
            const int k0 = ks * 16;
            const int kq = ks * 8;
            uint32_t a[2][4], bf[8][2];
#pragma unroll
            for (int mi = 0; mi < 2; ++mi) {
                const float* r0p = raw + (n0 + mi * 16 + gid) * RS + k0 + 2 * tig;
                const float* r1p = r0p + 8 * RS;
                float2 v0 = *(const float2*)r0p;
                float2 v1 = *(const float2*)r1p;
                float2 v2 = *(const float2*)(r0p + 8);
                float2 v3 = *(const float2*)(r1p + 8);
                a[mi][0] = pack_h2(v0.x, v0.y);
                a[mi][1] = pack_h2(v1.x, v1.y);
                a[mi][2] = pack_h2(v2.x, v2.y);
                a[mi][3] = pack_h2(v3.x, v3.y);
            }
#pragma unroll
            for (int ni = 0; ni < 8; ++ni) {
                int col = f0 + ni * 8 + gid;
                bf[ni][0] = __ldg(&g_W1h[(kq + tig)     * F_DIM + col]);
                bf[ni][1] = __ldg(&g_W1h[(kq + tig + 4) * F_DIM + col]);
            }
#pragma unroll
            for (int mi = 0; mi < 2; ++mi)
#pragma unroll
                for (int ni = 0; ni < 8; ++ni)
                    mma16(acc[mi * 8 + ni], a[mi], bf[ni]);
        }

        // ---- epi1: h = fp16(ssp(D1 + b1)) -> half2 SMEM [n][kp] ----
#pragma unroll
        for (int mi = 0; mi < 2; ++mi)
#pragma unroll
            for (int ni = 0; ni < 8; ++ni) {
                float* d = acc[mi * 8 + ni];
                int f = f0 + ni * 8 + 2 * tig;
                int n = n0 + mi * 16 + gid;
                int kp = f >> 1;
                float bb0 = b1s[f], bb1 = b1s[f + 1];
                h2[n * HS2 + kp]       = pack_h2(ssp(d[0] + bb0), ssp(d[1] + bb1));
                h2[(n + 8) * HS2 + kp] = pack_h2(ssp(d[2] + bb0), ssp(d[3] + bb1));
            }
        __syncthreads();               // sync 2: h complete

        // ================= GEMM2: K=128 (8 k-steps of 16) =================
#pragma unroll
        for (int t = 0; t < 16; ++t) { acc[t][0]=acc[t][1]=acc[t][2]=acc[t][3]=0.f; }

#pragma unroll
        for (int ks = 0; ks < 8; ++ks) {
            const int kq = ks * 8;
            uint32_t a[2][4], bf[8][2];
#pragma unroll
            for (int mi = 0; mi < 2; ++mi) {
                int r = (n0 + mi * 16 + gid) * HS2 + kq + tig;
                a[mi][0] = h2[r];
                a[mi][1] = h2[r + 8 * HS2];
                a[mi][2] = h2[r + 4];
                a[mi][3] = h2[r + 8 * HS2 + 4];
            }
#pragma unroll
            for (int ni = 0; ni < 8; ++ni) {
                int col = f0 + ni * 8 + gid;
                bf[ni][0] = __ldg(&g_W2h[(kq + tig)     * F_DIM + col]);
                bf[ni][1] = __ldg(&g_W2h[(kq + tig + 4) * F_DIM + col]);
            }
#pragma unroll
            for (int mi = 0; mi < 2; ++mi)
#pragma unroll
                for (int ni = 0; ni < 8; ++ni)
                    mma16(acc[mi * 8 + ni], a[mi], bf[ni]);
        }
        __syncthreads();               // sync 3: h2 reads done, may overwrite

        // ---- epi2: Wm = fp16((D2 + b2) * mask) -> h2 (all 128 rows) ----
#pragma unroll
        for (int mi = 0; mi < 2; ++mi)
#pragma unroll
            for (int ni = 0; ni < 8; ++ni) {
                float* d = acc[mi * 8 + ni];
                int f = f0 + ni * 8 + 2 * tig;
                int n = n0 + mi * 16 + gid;
                int kp = f >> 1;
                float bb0 = b2s[f], bb1 = b2s[f + 1];
                float m0 = msk_c[n], m1 = msk_c[n + 8];
                h2[n * HS2 + kp]       = pack_h2((d[0] + bb0) * m0, (d[1] + bb1) * m0);
                h2[(n + 8) * HS2 + kp] = pack_h2((d[2] + bb0) * m1, (d[3] + bb1) * m1);
            }
        __syncthreads();               // sync 4: Wm complete

        // ---- reduce: y[atom, f] = sum_n Wm[n,f] * xw[nbr[n], f] ----
        {
            const int at = tid >> 7, f = tid & 127;
            const int kp = f >> 1, hi = f & 1;
            const float* xwb = g_xw + (size_t)b * A_DIM * F_DIM + f;
            float y = 0.0f;
#pragma unroll 8
            for (int j = 0; j < 64; ++j) {
                int n = at * 64 + j;
                __half2 hh = *reinterpret_cast<const __half2*>(&h2[n * HS2 + kp]);
                float2 wv = __half22float2(hh);
                float w = hi ? wv.y : wv.x;
                float xv = __ldg(xwb + (size_t)nbr_c[n] * F_DIM);
                y = fmaf(w, xv, y);
            }
            g_y[(size_t)(p * 2 + at) * F_DIM + f] = y;
        }

        buf ^= 1;
    }
}

// ---------------------------------------------------------------------------
// Inputs: x, pairwise_mask, neighbors, f_ij, W_f1, b_f1, W_f2, b_f2,
//         W_in2f, W_f2out, b_f2out
// ---------------------------------------------------------------------------
extern "C" void kernel_launch(void* const* d_in, const int* in_sizes, int n_in,
                              void* d_out, int out_size)
{
    const float* x      = (const float*)d_in[0];
    const float* mask   = (const float*)d_in[1];
    const int*   nbrs   = (const int*)  d_in[2];
    const float* f_ij   = (const float*)d_in[3];
    const float* W_f1   = (const float*)d_in[4];
    const float* b_f1   = (const float*)d_in[5];
    const float* W_f2   = (const float*)d_in[6];
    const float* b_f2   = (const float*)d_in[7];
    const float* W_in2f = (const float*)d_in[8];
    const float* W_out  = (const float*)d_in[9];
    const float* b_out  = (const float*)d_in[10];
    float*       out    = (float*)d_out;

    const int BA = in_sizes[0] / F_DIM;   // 8192

    static float* xw_ptr = nullptr;
    static float* y_ptr  = nullptr;
    static int    nsm    = 0;
    if (!xw_ptr) {
        cudaGetSymbolAddress((void**)&xw_ptr, g_xw);
        cudaGetSymbolAddress((void**)&y_ptr,  g_y);
        cudaDeviceGetAttribute(&nsm, cudaDevAttrMultiProcessorCount, 0);
        cudaFuncSetAttribute(cfconv_mma, cudaFuncAttributeMaxDynamicSharedMemorySize, SMEM_TOTAL);
    }

    prep_kernel<<<1, 256>>>(W_f1, W_f2);
    dense_kernel<<<BA / 16, F_DIM>>>(x, W_in2f, nullptr, xw_ptr, 0);    // xw = x @ W_in2f
    cfconv_mma<<<2 * nsm, 256, SMEM_TOTAL>>>(f_ij, mask, nbrs, b_f1, b_f2);
    dense_kernel<<<BA / 16, F_DIM>>>(y_ptr, W_out, b_out, out, 1);      // out = ssp(y @ W_out + b)
}